// round 1
// baseline (speedup 1.0000x reference)
#include <cuda_runtime.h>
#include <math.h>

#define POOLN 7
#define NROIS 4
#define FEAT 2048
#define RED 512
#define FLATN (RED * 49)      // 25088
#define H1N 4096
#define H2N 2048
#define NCLS 21
#define NREG 80
#define IMG 128

// ---------------- scratch (device globals; no allocations allowed) -------
__device__ float g_pooled[NROIS * 49 * FEAT];   // [r][ph][pw][c]  c fastest
__device__ float g_flat[NROIS * FLATN];         // [r][o*49 + ph*7 + pw]
__device__ float g_h1[NROIS * H1N];
__device__ float g_h2[NROIS * H2N];

__device__ __forceinline__ float wsum(float v) {
#pragma unroll
    for (int o = 16; o > 0; o >>= 1) v += __shfl_xor_sync(0xffffffffu, v, o);
    return v;
}

// ---------------- kernel 1: ROI adaptive avg pool -------------------------
// grid = NROIS*FEAT blocks (r in low 2 bits for L2 reuse of overlapping
// crops), 224 threads = 7 warps, warp ph handles one output row of bins.
__global__ __launch_bounds__(224) void pool_kernel(
    const float* __restrict__ x, const int* __restrict__ rois) {
    int blk = blockIdx.x;
    int r = blk & 3;
    int c = blk >> 2;
    int wid = threadIdx.x >> 5;
    int lane = threadIdx.x & 31;

    int x0 = rois[r * 4 + 0];
    int y0 = rois[r * 4 + 1];
    int hh = rois[r * 4 + 2];   // cols count (y:y+h)
    int ww = rois[r * 4 + 3];   // rows count (x:x+w)
    int Hc = ww;                // crop axis1 (rows)
    int Wc = hh;                // crop axis2 (cols)

    int ph = wid;               // 0..6
    int hs = (ph * Hc) / 7;
    int he = ((ph + 1) * Hc + 6) / 7;

    float acc[7];
#pragma unroll
    for (int pw = 0; pw < 7; pw++) acc[pw] = 0.f;

    const float* base = x + (size_t)c * (IMG * IMG) + (size_t)x0 * IMG + y0;

    for (int b = lane; b < Wc; b += 32) {
        const float* col = base + b;
        float s0 = 0.f, s1 = 0.f;
        int a = hs;
        for (; a + 1 < he; a += 2) {
            s0 += col[a * IMG];
            s1 += col[(a + 1) * IMG];
        }
        if (a < he) s0 += col[a * IMG];
        float s = s0 + s1;
#pragma unroll
        for (int pw = 0; pw < 7; pw++) {
            int ws = (pw * Wc) / 7;
            int we = ((pw + 1) * Wc + 6) / 7;
            if (b >= ws && b < we) acc[pw] += s;
        }
    }

#pragma unroll
    for (int pw = 0; pw < 7; pw++) {
        float v = wsum(acc[pw]);
        if (lane == 0) {
            int ws = (pw * Wc) / 7;
            int we = ((pw + 1) * Wc + 6) / 7;
            float area = (float)((he - hs) * (we - ws));
            g_pooled[((r * 7 + ph) * 7 + pw) * FEAT + c] = v / area;
        }
    }
}

// ---------------- kernel 2: 1x1 conv (einsum rchw,oc->rohw) ---------------
// grid = 4r * 7ph * 16 o-splits = 448 blocks, 256 threads.
// Each warp owns 4 consecutive o; pooled slice streamed via 14KB smem chunks.
__global__ __launch_bounds__(256) void conv_kernel(
    const float* __restrict__ conv_w, const float* __restrict__ conv_b) {
    __shared__ float sm[7 * 512];
    int blk = blockIdx.x;
    int r = blk / 112;
    int rem = blk - r * 112;
    int ph = rem / 16;
    int os = rem - ph * 16;
    int wid = threadIdx.x >> 5;
    int lane = threadIdx.x & 31;
    int o = os * 32 + wid * 4;

    float acc[4][7];
#pragma unroll
    for (int j = 0; j < 4; j++)
#pragma unroll
        for (int pw = 0; pw < 7; pw++) acc[j][pw] = 0.f;

    const float* src = g_pooled + (size_t)(r * 7 + ph) * 7 * FEAT;

    for (int kc = 0; kc < 4; kc++) {
        __syncthreads();
        for (int i = threadIdx.x; i < 7 * 512; i += 256) {
            int pw = i >> 9;
            int kk = i & 511;
            sm[i] = src[pw * FEAT + kc * 512 + kk];
        }
        __syncthreads();
#pragma unroll
        for (int k = lane * 4; k < 512; k += 128) {
            float4 p[7];
#pragma unroll
            for (int pw = 0; pw < 7; pw++)
                p[pw] = *(const float4*)(sm + pw * 512 + k);
#pragma unroll
            for (int j = 0; j < 4; j++) {
                float4 w = *(const float4*)(conv_w + (size_t)(o + j) * FEAT + kc * 512 + k);
#pragma unroll
                for (int pw = 0; pw < 7; pw++) {
                    acc[j][pw] += w.x * p[pw].x + w.y * p[pw].y +
                                  w.z * p[pw].z + w.w * p[pw].w;
                }
            }
        }
    }

#pragma unroll
    for (int j = 0; j < 4; j++)
#pragma unroll
        for (int pw = 0; pw < 7; pw++) acc[j][pw] = wsum(acc[j][pw]);

    if (lane == 0) {
#pragma unroll
        for (int j = 0; j < 4; j++) {
            float b = conv_b[o + j];
#pragma unroll
            for (int pw = 0; pw < 7; pw++)
                g_flat[(size_t)r * FLATN + (o + j) * 49 + ph * 7 + pw] =
                    acc[j][pw] + b;
        }
    }
}

// ---------------- kernel 3: dense1 (K=25088, 4096 out) + ReLU -------------
// grid = 128 blocks * 32 j each; 8 warps * 4 j; flat panel chunked in smem.
// Each d1_w element (411MB, streamed once from HBM) feeds 4 batch-row FMAs.
__global__ __launch_bounds__(256) void d1_kernel(
    const float* __restrict__ d1_w, const float* __restrict__ d1_b) {
    __shared__ float smf[4 * 1792];   // 28 KB
    int wid = threadIdx.x >> 5;
    int lane = threadIdx.x & 31;
    int j0 = blockIdx.x * 32 + wid * 4;

    float acc[4][4];
#pragma unroll
    for (int j = 0; j < 4; j++)
#pragma unroll
        for (int rr = 0; rr < 4; rr++) acc[j][rr] = 0.f;

    for (int ch = 0; ch < 14; ch++) {
        int kb = ch * 1792;
        __syncthreads();
        for (int i = threadIdx.x; i < 4 * 1792; i += 256) {
            int rr = i / 1792;
            int kk = i - rr * 1792;
            smf[i] = g_flat[(size_t)rr * FLATN + kb + kk];
        }
        __syncthreads();
#pragma unroll
        for (int k = lane * 4; k < 1792; k += 128) {   // 14 iters
            float4 f[4];
#pragma unroll
            for (int rr = 0; rr < 4; rr++)
                f[rr] = *(const float4*)(smf + rr * 1792 + k);
#pragma unroll
            for (int j = 0; j < 4; j++) {
                float4 w = *(const float4*)(d1_w + (size_t)(j0 + j) * FLATN + kb + k);
#pragma unroll
                for (int rr = 0; rr < 4; rr++) {
                    acc[j][rr] += w.x * f[rr].x + w.y * f[rr].y +
                                  w.z * f[rr].z + w.w * f[rr].w;
                }
            }
        }
    }

#pragma unroll
    for (int j = 0; j < 4; j++)
#pragma unroll
        for (int rr = 0; rr < 4; rr++) acc[j][rr] = wsum(acc[j][rr]);

    if (lane == 0) {
#pragma unroll
        for (int j = 0; j < 4; j++) {
            float b = d1_b[j0 + j];
#pragma unroll
            for (int rr = 0; rr < 4; rr++)
                g_h1[rr * H1N + j0 + j] = fmaxf(acc[j][rr] + b, 0.f);
        }
    }
}

// ---------------- kernel 4: dense2 (K=4096, 2048 out) + ReLU --------------
__global__ __launch_bounds__(256) void d2_kernel(
    const float* __restrict__ d2_w, const float* __restrict__ d2_b) {
    __shared__ float smh[4 * 2048];   // 32 KB
    int wid = threadIdx.x >> 5;
    int lane = threadIdx.x & 31;
    int i0 = blockIdx.x * 16 + wid * 2;

    float acc[2][4];
#pragma unroll
    for (int j = 0; j < 2; j++)
#pragma unroll
        for (int rr = 0; rr < 4; rr++) acc[j][rr] = 0.f;

    for (int ch = 0; ch < 2; ch++) {
        int kb = ch * 2048;
        __syncthreads();
        for (int i = threadIdx.x; i < 4 * 2048; i += 256) {
            int rr = i >> 11;
            int kk = i & 2047;
            smh[i] = g_h1[rr * H1N + kb + kk];
        }
        __syncthreads();
#pragma unroll
        for (int k = lane * 4; k < 2048; k += 128) {   // 16 iters
            float4 f[4];
#pragma unroll
            for (int rr = 0; rr < 4; rr++)
                f[rr] = *(const float4*)(smh + rr * 2048 + k);
#pragma unroll
            for (int j = 0; j < 2; j++) {
                float4 w = *(const float4*)(d2_w + (size_t)(i0 + j) * H1N + kb + k);
#pragma unroll
                for (int rr = 0; rr < 4; rr++) {
                    acc[j][rr] += w.x * f[rr].x + w.y * f[rr].y +
                                  w.z * f[rr].z + w.w * f[rr].w;
                }
            }
        }
    }

#pragma unroll
    for (int j = 0; j < 2; j++)
#pragma unroll
        for (int rr = 0; rr < 4; rr++) acc[j][rr] = wsum(acc[j][rr]);

    if (lane == 0) {
#pragma unroll
        for (int j = 0; j < 2; j++) {
            float b = d2_b[i0 + j];
#pragma unroll
            for (int rr = 0; rr < 4; rr++)
                g_h2[rr * H2N + i0 + j] = fmaxf(acc[j][rr] + b, 0.f);
        }
    }
}

// ---------------- kernel 5: class softmax + regr heads --------------------
// grid = 4 (one block per roi), 256 threads.
__global__ __launch_bounds__(256) void head_kernel(
    const float* __restrict__ d3_w, const float* __restrict__ d4_w,
    float* __restrict__ out) {
    __shared__ float smh[H2N];
    __shared__ float slog[NCLS];
    int r = blockIdx.x;
    int wid = threadIdx.x >> 5;
    int lane = threadIdx.x & 31;

    for (int i = threadIdx.x; i < H2N; i += 256) smh[i] = g_h2[r * H2N + i];
    __syncthreads();

    for (int row = wid; row < NCLS + NREG; row += 8) {
        const float* wrow = (row < NCLS)
                                ? d3_w + (size_t)row * H2N
                                : d4_w + (size_t)(row - NCLS) * H2N;
        float a = 0.f;
#pragma unroll
        for (int k = lane * 4; k < H2N; k += 128) {
            float4 w = *(const float4*)(wrow + k);
            float4 f = *(const float4*)(smh + k);
            a += w.x * f.x + w.y * f.y + w.z * f.z + w.w * f.w;
        }
        a = wsum(a);
        if (lane == 0) {
            if (row < NCLS) slog[row] = a;
            else out[NROIS * NCLS + r * NREG + (row - NCLS)] = a;
        }
    }
    __syncthreads();

    if (wid == 0) {
        float v = (lane < NCLS) ? slog[lane] : -INFINITY;
        float m = v;
#pragma unroll
        for (int o = 16; o > 0; o >>= 1)
            m = fmaxf(m, __shfl_xor_sync(0xffffffffu, m, o));
        float e = (lane < NCLS) ? expf(v - m) : 0.f;
        float s = wsum(e);
        if (lane < NCLS) out[r * NCLS + lane] = e / s;
    }
}

// ---------------- launch ---------------------------------------------------
extern "C" void kernel_launch(void* const* d_in, const int* in_sizes, int n_in,
                              void* d_out, int out_size) {
    const float* base_x = (const float*)d_in[0];
    const int*   rois   = (const int*)d_in[1];
    const float* conv_w = (const float*)d_in[2];
    const float* conv_b = (const float*)d_in[3];
    const float* d1_w   = (const float*)d_in[4];
    const float* d1_b   = (const float*)d_in[5];
    const float* d2_w   = (const float*)d_in[6];
    const float* d2_b   = (const float*)d_in[7];
    const float* d3_w   = (const float*)d_in[8];
    const float* d4_w   = (const float*)d_in[9];
    float* out = (float*)d_out;

    pool_kernel<<<NROIS * FEAT, 224>>>(base_x, rois);
    conv_kernel<<<448, 256>>>(conv_w, conv_b);
    d1_kernel<<<128, 256>>>(d1_w, d1_b);
    d2_kernel<<<128, 256>>>(d2_w, d2_b);
    head_kernel<<<NROIS, 256>>>(d3_w, d4_w, out);
}

// round 2
// speedup vs baseline: 1.1444x; 1.1444x over previous
#include <cuda_runtime.h>
#include <math.h>

#define POOLN 7
#define NROIS 4
#define FEAT 2048
#define RED 512
#define FLATN (RED * 49)      // 25088
#define H1N 4096
#define H2N 2048
#define NCLS 21
#define NREG 80
#define IMG 128

// ---------------- scratch (device globals; no allocations allowed) -------
__device__ float g_pooled[NROIS * 49 * FEAT];   // [r][ph][pw][c]  c fastest
__device__ float g_flat[NROIS * FLATN];         // [r][o*49 + ph*7 + pw]
__device__ float g_h1[NROIS * H1N];
__device__ float g_h2[NROIS * H2N];

__device__ __forceinline__ float wsum(float v) {
#pragma unroll
    for (int o = 16; o > 0; o >>= 1) v += __shfl_xor_sync(0xffffffffu, v, o);
    return v;
}

// ---------------- kernel 1: ROI adaptive avg pool -------------------------
// grid = NROIS*FEAT blocks (r in low 2 bits for L2 reuse of overlapping
// crops), 224 threads = 7 warps, warp ph handles one output row of bins.
__global__ __launch_bounds__(224) void pool_kernel(
    const float* __restrict__ x, const int* __restrict__ rois) {
    int blk = blockIdx.x;
    int r = blk & 3;
    int c = blk >> 2;
    int wid = threadIdx.x >> 5;
    int lane = threadIdx.x & 31;

    int x0 = rois[r * 4 + 0];
    int y0 = rois[r * 4 + 1];
    int hh = rois[r * 4 + 2];   // cols count (y:y+h)
    int ww = rois[r * 4 + 3];   // rows count (x:x+w)
    int Hc = ww;                // crop axis1 (rows)
    int Wc = hh;                // crop axis2 (cols)

    int ph = wid;               // 0..6
    int hs = (ph * Hc) / 7;
    int he = ((ph + 1) * Hc + 6) / 7;

    float acc[7];
#pragma unroll
    for (int pw = 0; pw < 7; pw++) acc[pw] = 0.f;

    const float* base = x + (size_t)c * (IMG * IMG) + (size_t)x0 * IMG + y0;

    for (int b = lane; b < Wc; b += 32) {
        const float* col = base + b;
        float s0 = 0.f, s1 = 0.f, s2 = 0.f, s3 = 0.f;
        int a = hs;
        for (; a + 3 < he; a += 4) {
            s0 += col[(a + 0) * IMG];
            s1 += col[(a + 1) * IMG];
            s2 += col[(a + 2) * IMG];
            s3 += col[(a + 3) * IMG];
        }
        for (; a < he; a++) s0 += col[a * IMG];
        float s = (s0 + s1) + (s2 + s3);
#pragma unroll
        for (int pw = 0; pw < 7; pw++) {
            int ws = (pw * Wc) / 7;
            int we = ((pw + 1) * Wc + 6) / 7;
            if (b >= ws && b < we) acc[pw] += s;
        }
    }

#pragma unroll
    for (int pw = 0; pw < 7; pw++) {
        float v = wsum(acc[pw]);
        if (lane == 0) {
            int ws = (pw * Wc) / 7;
            int we = ((pw + 1) * Wc + 6) / 7;
            float area = (float)((he - hs) * (we - ws));
            g_pooled[((r * 7 + ph) * 7 + pw) * FEAT + c] = v / area;
        }
    }
}

// ---------------- kernel 2: 1x1 conv (einsum rchw,oc->rohw) ---------------
// grid = 4r * 7ph * 16 o-splits = 448 blocks, 256 threads.
__global__ __launch_bounds__(256) void conv_kernel(
    const float* __restrict__ conv_w, const float* __restrict__ conv_b) {
    __shared__ float sm[7 * 512];
    int blk = blockIdx.x;
    int r = blk / 112;
    int rem = blk - r * 112;
    int ph = rem / 16;
    int os = rem - ph * 16;
    int wid = threadIdx.x >> 5;
    int lane = threadIdx.x & 31;
    int o = os * 32 + wid * 4;

    float acc[4][7];
#pragma unroll
    for (int j = 0; j < 4; j++)
#pragma unroll
        for (int pw = 0; pw < 7; pw++) acc[j][pw] = 0.f;

    const float* src = g_pooled + (size_t)(r * 7 + ph) * 7 * FEAT;

    for (int kc = 0; kc < 4; kc++) {
        __syncthreads();
        for (int i = threadIdx.x; i < 7 * 512; i += 256) {
            int pw = i >> 9;
            int kk = i & 511;
            sm[i] = src[pw * FEAT + kc * 512 + kk];
        }
        __syncthreads();
#pragma unroll
        for (int k = lane * 4; k < 512; k += 128) {
            float4 p[7];
#pragma unroll
            for (int pw = 0; pw < 7; pw++)
                p[pw] = *(const float4*)(sm + pw * 512 + k);
#pragma unroll
            for (int j = 0; j < 4; j++) {
                float4 w = *(const float4*)(conv_w + (size_t)(o + j) * FEAT + kc * 512 + k);
#pragma unroll
                for (int pw = 0; pw < 7; pw++) {
                    acc[j][pw] += w.x * p[pw].x + w.y * p[pw].y +
                                  w.z * p[pw].z + w.w * p[pw].w;
                }
            }
        }
    }

#pragma unroll
    for (int j = 0; j < 4; j++)
#pragma unroll
        for (int pw = 0; pw < 7; pw++) acc[j][pw] = wsum(acc[j][pw]);

    if (lane == 0) {
#pragma unroll
        for (int j = 0; j < 4; j++) {
            float b = conv_b[o + j];
#pragma unroll
            for (int pw = 0; pw < 7; pw++)
                g_flat[(size_t)r * FLATN + (o + j) * 49 + ph * 7 + pw] =
                    acc[j][pw] + b;
        }
    }
}

// ---------------- kernel 3: dense1 (K=25088, 4096 out) + ReLU -------------
// 512 blocks x 8 warps; each warp owns ONE output row j, all 4 batch rows.
// K chunked 14 x 1792 through 28KB smem. Weight LDG.128 stream per warp is
// contiguous 7KB per chunk, 14 independent loads fully unrolled -> high MLP.
__global__ __launch_bounds__(256) void d1_kernel(
    const float* __restrict__ d1_w, const float* __restrict__ d1_b) {
    __shared__ float smf[4 * 1792];   // 28 KB
    int wid = threadIdx.x >> 5;
    int lane = threadIdx.x & 31;
    int j = blockIdx.x * 8 + wid;

    float a0 = 0.f, a1 = 0.f, a2 = 0.f, a3 = 0.f;

    for (int ch = 0; ch < 14; ch++) {
        int kb = ch * 1792;
        __syncthreads();
        for (int i = threadIdx.x; i < 4 * 1792; i += 256) {
            int rr = i / 1792;
            int kk = i - rr * 1792;
            smf[i] = g_flat[(size_t)rr * FLATN + kb + kk];
        }
        __syncthreads();
        const float* wp = d1_w + (size_t)j * FLATN + kb;
#pragma unroll
        for (int it = 0; it < 14; it++) {
            int k = lane * 4 + it * 128;
            float4 w = *(const float4*)(wp + k);
            float4 f0 = *(const float4*)(smf + 0 * 1792 + k);
            float4 f1 = *(const float4*)(smf + 1 * 1792 + k);
            float4 f2 = *(const float4*)(smf + 2 * 1792 + k);
            float4 f3 = *(const float4*)(smf + 3 * 1792 + k);
            a0 += w.x * f0.x + w.y * f0.y + w.z * f0.z + w.w * f0.w;
            a1 += w.x * f1.x + w.y * f1.y + w.z * f1.z + w.w * f1.w;
            a2 += w.x * f2.x + w.y * f2.y + w.z * f2.z + w.w * f2.w;
            a3 += w.x * f3.x + w.y * f3.y + w.z * f3.z + w.w * f3.w;
        }
    }

    a0 = wsum(a0); a1 = wsum(a1); a2 = wsum(a2); a3 = wsum(a3);
    if (lane == 0) {
        float b = d1_b[j];
        g_h1[0 * H1N + j] = fmaxf(a0 + b, 0.f);
        g_h1[1 * H1N + j] = fmaxf(a1 + b, 0.f);
        g_h1[2 * H1N + j] = fmaxf(a2 + b, 0.f);
        g_h1[3 * H1N + j] = fmaxf(a3 + b, 0.f);
    }
}

// ---------------- kernel 4: dense2 (K=4096, 2048 out) + ReLU --------------
// 256 blocks x 8 warps, one output row per warp, K in 2 x 2048 chunks.
__global__ __launch_bounds__(256) void d2_kernel(
    const float* __restrict__ d2_w, const float* __restrict__ d2_b) {
    __shared__ float smh[4 * 2048];   // 32 KB
    int wid = threadIdx.x >> 5;
    int lane = threadIdx.x & 31;
    int j = blockIdx.x * 8 + wid;

    float a0 = 0.f, a1 = 0.f, a2 = 0.f, a3 = 0.f;

    for (int ch = 0; ch < 2; ch++) {
        int kb = ch * 2048;
        __syncthreads();
        for (int i = threadIdx.x; i < 4 * 2048; i += 256) {
            int rr = i >> 11;
            int kk = i & 2047;
            smh[i] = g_h1[rr * H1N + kb + kk];
        }
        __syncthreads();
        const float* wp = d2_w + (size_t)j * H1N + kb;
#pragma unroll
        for (int it = 0; it < 16; it++) {
            int k = lane * 4 + it * 128;
            float4 w = *(const float4*)(wp + k);
            float4 f0 = *(const float4*)(smh + 0 * 2048 + k);
            float4 f1 = *(const float4*)(smh + 1 * 2048 + k);
            float4 f2 = *(const float4*)(smh + 2 * 2048 + k);
            float4 f3 = *(const float4*)(smh + 3 * 2048 + k);
            a0 += w.x * f0.x + w.y * f0.y + w.z * f0.z + w.w * f0.w;
            a1 += w.x * f1.x + w.y * f1.y + w.z * f1.z + w.w * f1.w;
            a2 += w.x * f2.x + w.y * f2.y + w.z * f2.z + w.w * f2.w;
            a3 += w.x * f3.x + w.y * f3.y + w.z * f3.z + w.w * f3.w;
        }
    }

    a0 = wsum(a0); a1 = wsum(a1); a2 = wsum(a2); a3 = wsum(a3);
    if (lane == 0) {
        float b = d2_b[j];
        g_h2[0 * H2N + j] = fmaxf(a0 + b, 0.f);
        g_h2[1 * H2N + j] = fmaxf(a1 + b, 0.f);
        g_h2[2 * H2N + j] = fmaxf(a2 + b, 0.f);
        g_h2[3 * H2N + j] = fmaxf(a3 + b, 0.f);
    }
}

// ---------------- kernel 5: class softmax + regr heads --------------------
__global__ __launch_bounds__(256) void head_kernel(
    const float* __restrict__ d3_w, const float* __restrict__ d4_w,
    float* __restrict__ out) {
    __shared__ float smh[H2N];
    __shared__ float slog[NCLS];
    int r = blockIdx.x;
    int wid = threadIdx.x >> 5;
    int lane = threadIdx.x & 31;

    for (int i = threadIdx.x; i < H2N; i += 256) smh[i] = g_h2[r * H2N + i];
    __syncthreads();

    for (int row = wid; row < NCLS + NREG; row += 8) {
        const float* wrow = (row < NCLS)
                                ? d3_w + (size_t)row * H2N
                                : d4_w + (size_t)(row - NCLS) * H2N;
        float a = 0.f;
#pragma unroll
        for (int k = lane * 4; k < H2N; k += 128) {
            float4 w = *(const float4*)(wrow + k);
            float4 f = *(const float4*)(smh + k);
            a += w.x * f.x + w.y * f.y + w.z * f.z + w.w * f.w;
        }
        a = wsum(a);
        if (lane == 0) {
            if (row < NCLS) slog[row] = a;
            else out[NROIS * NCLS + r * NREG + (row - NCLS)] = a;
        }
    }
    __syncthreads();

    if (wid == 0) {
        float v = (lane < NCLS) ? slog[lane] : -INFINITY;
        float m = v;
#pragma unroll
        for (int o = 16; o > 0; o >>= 1)
            m = fmaxf(m, __shfl_xor_sync(0xffffffffu, m, o));
        float e = (lane < NCLS) ? expf(v - m) : 0.f;
        float s = wsum(e);
        if (lane < NCLS) out[r * NCLS + lane] = e / s;
    }
}

// ---------------- launch ---------------------------------------------------
extern "C" void kernel_launch(void* const* d_in, const int* in_sizes, int n_in,
                              void* d_out, int out_size) {
    const float* base_x = (const float*)d_in[0];
    const int*   rois   = (const int*)d_in[1];
    const float* conv_w = (const float*)d_in[2];
    const float* conv_b = (const float*)d_in[3];
    const float* d1_w   = (const float*)d_in[4];
    const float* d1_b   = (const float*)d_in[5];
    const float* d2_w   = (const float*)d_in[6];
    const float* d2_b   = (const float*)d_in[7];
    const float* d3_w   = (const float*)d_in[8];
    const float* d4_w   = (const float*)d_in[9];
    float* out = (float*)d_out;

    pool_kernel<<<NROIS * FEAT, 224>>>(base_x, rois);
    conv_kernel<<<448, 256>>>(conv_w, conv_b);
    d1_kernel<<<512, 256>>>(d1_w, d1_b);
    d2_kernel<<<256, 256>>>(d2_w, d2_b);
    head_kernel<<<NROIS, 256>>>(d3_w, d4_w, out);
}

// round 3
// speedup vs baseline: 1.4266x; 1.2467x over previous
#include <cuda_runtime.h>
#include <math.h>

#define POOLN 7
#define NROIS 4
#define FEAT 2048
#define RED 512
#define FLATN (RED * 49)      // 25088 = 14 * 1792
#define H1N 4096
#define H2N 2048
#define NCLS 21
#define NREG 80
#define IMG 128

#define D1_CHUNK 1792
#define D1_KSPLIT 7           // 7 splits * 2 chunks * 1792 = 25088
#define D1_CH_PER_SPLIT 2

// ---------------- scratch (device globals; no allocations allowed) -------
__device__ float g_pooled[NROIS * 49 * FEAT];   // [r][ph][pw][c]  c fastest
__device__ float g_flat[NROIS * FLATN];         // [r][o*49 + ph*7 + pw]
__device__ float g_h1[NROIS * H1N];             // pre-relu, bias-seeded
__device__ float g_h2[NROIS * H2N];             // pre-relu, bias-seeded

__device__ __forceinline__ float wsum(float v) {
#pragma unroll
    for (int o = 16; o > 0; o >>= 1) v += __shfl_xor_sync(0xffffffffu, v, o);
    return v;
}

// ---------------- kernel 0: seed h1/h2 with biases -------------------------
__global__ __launch_bounds__(256) void init_kernel(
    const float* __restrict__ d1_b, const float* __restrict__ d2_b) {
    int i = blockIdx.x * 256 + threadIdx.x;
    if (i < H1N) {
        float b = d1_b[i];
#pragma unroll
        for (int rr = 0; rr < 4; rr++) g_h1[rr * H1N + i] = b;
    } else if (i < H1N + H2N) {
        int j = i - H1N;
        float b = d2_b[j];
#pragma unroll
        for (int rr = 0; rr < 4; rr++) g_h2[rr * H2N + j] = b;
    }
}

// ---------------- kernel 1: ROI adaptive avg pool -------------------------
__global__ __launch_bounds__(224) void pool_kernel(
    const float* __restrict__ x, const int* __restrict__ rois) {
    int blk = blockIdx.x;
    int r = blk & 3;
    int c = blk >> 2;
    int wid = threadIdx.x >> 5;
    int lane = threadIdx.x & 31;

    int x0 = rois[r * 4 + 0];
    int y0 = rois[r * 4 + 1];
    int hh = rois[r * 4 + 2];
    int ww = rois[r * 4 + 3];
    int Hc = ww;
    int Wc = hh;

    int ph = wid;
    int hs = (ph * Hc) / 7;
    int he = ((ph + 1) * Hc + 6) / 7;

    float acc[7];
#pragma unroll
    for (int pw = 0; pw < 7; pw++) acc[pw] = 0.f;

    const float* base = x + (size_t)c * (IMG * IMG) + (size_t)x0 * IMG + y0;

    for (int b = lane; b < Wc; b += 32) {
        const float* col = base + b;
        float s0 = 0.f, s1 = 0.f, s2 = 0.f, s3 = 0.f;
        int a = hs;
        for (; a + 3 < he; a += 4) {
            s0 += col[(a + 0) * IMG];
            s1 += col[(a + 1) * IMG];
            s2 += col[(a + 2) * IMG];
            s3 += col[(a + 3) * IMG];
        }
        for (; a < he; a++) s0 += col[a * IMG];
        float s = (s0 + s1) + (s2 + s3);
#pragma unroll
        for (int pw = 0; pw < 7; pw++) {
            int ws = (pw * Wc) / 7;
            int we = ((pw + 1) * Wc + 6) / 7;
            if (b >= ws && b < we) acc[pw] += s;
        }
    }

#pragma unroll
    for (int pw = 0; pw < 7; pw++) {
        float v = wsum(acc[pw]);
        if (lane == 0) {
            int ws = (pw * Wc) / 7;
            int we = ((pw + 1) * Wc + 6) / 7;
            float area = (float)((he - hs) * (we - ws));
            g_pooled[((r * 7 + ph) * 7 + pw) * FEAT + c] = v / area;
        }
    }
}

// ---------------- kernel 2: 1x1 conv (einsum rchw,oc->rohw) ---------------
__global__ __launch_bounds__(256) void conv_kernel(
    const float* __restrict__ conv_w, const float* __restrict__ conv_b) {
    __shared__ float sm[7 * 512];
    int blk = blockIdx.x;
    int r = blk / 112;
    int rem = blk - r * 112;
    int ph = rem / 16;
    int os = rem - ph * 16;
    int wid = threadIdx.x >> 5;
    int lane = threadIdx.x & 31;
    int o = os * 32 + wid * 4;

    float acc[4][7];
#pragma unroll
    for (int j = 0; j < 4; j++)
#pragma unroll
        for (int pw = 0; pw < 7; pw++) acc[j][pw] = 0.f;

    const float* src = g_pooled + (size_t)(r * 7 + ph) * 7 * FEAT;

    for (int kc = 0; kc < 4; kc++) {
        __syncthreads();
        for (int i = threadIdx.x; i < 7 * 512; i += 256) {
            int pw = i >> 9;
            int kk = i & 511;
            sm[i] = src[pw * FEAT + kc * 512 + kk];
        }
        __syncthreads();
#pragma unroll
        for (int k = lane * 4; k < 512; k += 128) {
            float4 p[7];
#pragma unroll
            for (int pw = 0; pw < 7; pw++)
                p[pw] = *(const float4*)(sm + pw * 512 + k);
#pragma unroll
            for (int j = 0; j < 4; j++) {
                float4 w = *(const float4*)(conv_w + (size_t)(o + j) * FEAT + kc * 512 + k);
#pragma unroll
                for (int pw = 0; pw < 7; pw++) {
                    acc[j][pw] += w.x * p[pw].x + w.y * p[pw].y +
                                  w.z * p[pw].z + w.w * p[pw].w;
                }
            }
        }
    }

#pragma unroll
    for (int j = 0; j < 4; j++)
#pragma unroll
        for (int pw = 0; pw < 7; pw++) acc[j][pw] = wsum(acc[j][pw]);

    if (lane == 0) {
#pragma unroll
        for (int j = 0; j < 4; j++) {
            float b = conv_b[o + j];
#pragma unroll
            for (int pw = 0; pw < 7; pw++)
                g_flat[(size_t)r * FLATN + (o + j) * 49 + ph * 7 + pw] =
                    acc[j][pw] + b;
        }
    }
}

// ---------------- kernel 3: dense1 (K=25088, 4096 out), K-split ----------
// grid = 256 row-blocks * 7 K-splits = 1792 blocks, 256 threads.
// Each warp owns 2 output rows (2 LDG.128 streams/iter); each block covers
// K-range of 2*1792. Partial sums atomicAdd into bias-seeded g_h1.
__global__ __launch_bounds__(256) void d1_kernel(const float* __restrict__ d1_w) {
    __shared__ float smf[4 * D1_CHUNK];   // 28 KB
    int ks = blockIdx.x % D1_KSPLIT;
    int rowblk = blockIdx.x / D1_KSPLIT;
    int wid = threadIdx.x >> 5;
    int lane = threadIdx.x & 31;
    int j0 = rowblk * 16 + wid * 2;
    int kb0 = ks * (D1_CH_PER_SPLIT * D1_CHUNK);

    float a00 = 0.f, a01 = 0.f, a02 = 0.f, a03 = 0.f;
    float a10 = 0.f, a11 = 0.f, a12 = 0.f, a13 = 0.f;

    for (int ch = 0; ch < D1_CH_PER_SPLIT; ch++) {
        int kb = kb0 + ch * D1_CHUNK;
        __syncthreads();
        for (int i = threadIdx.x; i < 4 * D1_CHUNK; i += 256) {
            int rr = i / D1_CHUNK;
            int kk = i - rr * D1_CHUNK;
            smf[i] = g_flat[(size_t)rr * FLATN + kb + kk];
        }
        __syncthreads();
        const float* wp0 = d1_w + (size_t)(j0 + 0) * FLATN + kb;
        const float* wp1 = d1_w + (size_t)(j0 + 1) * FLATN + kb;
#pragma unroll
        for (int it = 0; it < 14; it++) {
            int k = lane * 4 + it * 128;
            float4 w0 = *(const float4*)(wp0 + k);
            float4 w1 = *(const float4*)(wp1 + k);
            float4 f0 = *(const float4*)(smf + 0 * D1_CHUNK + k);
            float4 f1 = *(const float4*)(smf + 1 * D1_CHUNK + k);
            float4 f2 = *(const float4*)(smf + 2 * D1_CHUNK + k);
            float4 f3 = *(const float4*)(smf + 3 * D1_CHUNK + k);
            a00 += w0.x * f0.x + w0.y * f0.y + w0.z * f0.z + w0.w * f0.w;
            a01 += w0.x * f1.x + w0.y * f1.y + w0.z * f1.z + w0.w * f1.w;
            a02 += w0.x * f2.x + w0.y * f2.y + w0.z * f2.z + w0.w * f2.w;
            a03 += w0.x * f3.x + w0.y * f3.y + w0.z * f3.z + w0.w * f3.w;
            a10 += w1.x * f0.x + w1.y * f0.y + w1.z * f0.z + w1.w * f0.w;
            a11 += w1.x * f1.x + w1.y * f1.y + w1.z * f1.z + w1.w * f1.w;
            a12 += w1.x * f2.x + w1.y * f2.y + w1.z * f2.z + w1.w * f2.w;
            a13 += w1.x * f3.x + w1.y * f3.y + w1.z * f3.z + w1.w * f3.w;
        }
    }

    a00 = wsum(a00); a01 = wsum(a01); a02 = wsum(a02); a03 = wsum(a03);
    a10 = wsum(a10); a11 = wsum(a11); a12 = wsum(a12); a13 = wsum(a13);
    if (lane == 0) {
        atomicAdd(&g_h1[0 * H1N + j0 + 0], a00);
        atomicAdd(&g_h1[1 * H1N + j0 + 0], a01);
        atomicAdd(&g_h1[2 * H1N + j0 + 0], a02);
        atomicAdd(&g_h1[3 * H1N + j0 + 0], a03);
        atomicAdd(&g_h1[0 * H1N + j0 + 1], a10);
        atomicAdd(&g_h1[1 * H1N + j0 + 1], a11);
        atomicAdd(&g_h1[2 * H1N + j0 + 1], a12);
        atomicAdd(&g_h1[3 * H1N + j0 + 1], a13);
    }
}

// ---------------- kernel 4: dense2 (K=4096, 2048 out), K-split 2 ----------
// grid = 128 row-blocks * 2 K-splits = 256 blocks; 2 rows per warp.
// ReLU applied to h1 at smem load; partials atomicAdd into bias-seeded g_h2.
__global__ __launch_bounds__(256) void d2_kernel(const float* __restrict__ d2_w) {
    __shared__ float smh[4 * 2048];   // 32 KB
    int ks = blockIdx.x & 1;
    int rowblk = blockIdx.x >> 1;
    int wid = threadIdx.x >> 5;
    int lane = threadIdx.x & 31;
    int j0 = rowblk * 16 + wid * 2;
    int kb = ks * 2048;

    for (int i = threadIdx.x; i < 4 * 2048; i += 256) {
        int rr = i >> 11;
        int kk = i & 2047;
        smh[i] = fmaxf(g_h1[rr * H1N + kb + kk], 0.f);
    }
    __syncthreads();

    float a00 = 0.f, a01 = 0.f, a02 = 0.f, a03 = 0.f;
    float a10 = 0.f, a11 = 0.f, a12 = 0.f, a13 = 0.f;

    const float* wp0 = d2_w + (size_t)(j0 + 0) * H1N + kb;
    const float* wp1 = d2_w + (size_t)(j0 + 1) * H1N + kb;
#pragma unroll
    for (int it = 0; it < 16; it++) {
        int k = lane * 4 + it * 128;
        float4 w0 = *(const float4*)(wp0 + k);
        float4 w1 = *(const float4*)(wp1 + k);
        float4 f0 = *(const float4*)(smh + 0 * 2048 + k);
        float4 f1 = *(const float4*)(smh + 1 * 2048 + k);
        float4 f2 = *(const float4*)(smh + 2 * 2048 + k);
        float4 f3 = *(const float4*)(smh + 3 * 2048 + k);
        a00 += w0.x * f0.x + w0.y * f0.y + w0.z * f0.z + w0.w * f0.w;
        a01 += w0.x * f1.x + w0.y * f1.y + w0.z * f1.z + w0.w * f1.w;
        a02 += w0.x * f2.x + w0.y * f2.y + w0.z * f2.z + w0.w * f2.w;
        a03 += w0.x * f3.x + w0.y * f3.y + w0.z * f3.z + w0.w * f3.w;
        a10 += w1.x * f0.x + w1.y * f0.y + w1.z * f0.z + w1.w * f0.w;
        a11 += w1.x * f1.x + w1.y * f1.y + w1.z * f1.z + w1.w * f1.w;
        a12 += w1.x * f2.x + w1.y * f2.y + w1.z * f2.z + w1.w * f2.w;
        a13 += w1.x * f3.x + w1.y * f3.y + w1.z * f3.z + w1.w * f3.w;
    }

    a00 = wsum(a00); a01 = wsum(a01); a02 = wsum(a02); a03 = wsum(a03);
    a10 = wsum(a10); a11 = wsum(a11); a12 = wsum(a12); a13 = wsum(a13);
    if (lane == 0) {
        atomicAdd(&g_h2[0 * H2N + j0 + 0], a00);
        atomicAdd(&g_h2[1 * H2N + j0 + 0], a01);
        atomicAdd(&g_h2[2 * H2N + j0 + 0], a02);
        atomicAdd(&g_h2[3 * H2N + j0 + 0], a03);
        atomicAdd(&g_h2[0 * H2N + j0 + 1], a10);
        atomicAdd(&g_h2[1 * H2N + j0 + 1], a11);
        atomicAdd(&g_h2[2 * H2N + j0 + 1], a12);
        atomicAdd(&g_h2[3 * H2N + j0 + 1], a13);
    }
}

// ---------------- kernel 5: class softmax + regr heads --------------------
__global__ __launch_bounds__(256) void head_kernel(
    const float* __restrict__ d3_w, const float* __restrict__ d4_w,
    float* __restrict__ out) {
    __shared__ float smh[H2N];
    __shared__ float slog[NCLS];
    int r = blockIdx.x;
    int wid = threadIdx.x >> 5;
    int lane = threadIdx.x & 31;

    for (int i = threadIdx.x; i < H2N; i += 256)
        smh[i] = fmaxf(g_h2[r * H2N + i], 0.f);
    __syncthreads();

    for (int row = wid; row < NCLS + NREG; row += 8) {
        const float* wrow = (row < NCLS)
                                ? d3_w + (size_t)row * H2N
                                : d4_w + (size_t)(row - NCLS) * H2N;
        float a = 0.f;
#pragma unroll
        for (int k = lane * 4; k < H2N; k += 128) {
            float4 w = *(const float4*)(wrow + k);
            float4 f = *(const float4*)(smh + k);
            a += w.x * f.x + w.y * f.y + w.z * f.z + w.w * f.w;
        }
        a = wsum(a);
        if (lane == 0) {
            if (row < NCLS) slog[row] = a;
            else out[NROIS * NCLS + r * NREG + (row - NCLS)] = a;
        }
    }
    __syncthreads();

    if (wid == 0) {
        float v = (lane < NCLS) ? slog[lane] : -INFINITY;
        float m = v;
#pragma unroll
        for (int o = 16; o > 0; o >>= 1)
            m = fmaxf(m, __shfl_xor_sync(0xffffffffu, m, o));
        float e = (lane < NCLS) ? expf(v - m) : 0.f;
        float s = wsum(e);
        if (lane < NCLS) out[r * NCLS + lane] = e / s;
    }
}

// ---------------- launch ---------------------------------------------------
extern "C" void kernel_launch(void* const* d_in, const int* in_sizes, int n_in,
                              void* d_out, int out_size) {
    const float* base_x = (const float*)d_in[0];
    const int*   rois   = (const int*)d_in[1];
    const float* conv_w = (const float*)d_in[2];
    const float* conv_b = (const float*)d_in[3];
    const float* d1_w   = (const float*)d_in[4];
    const float* d1_b   = (const float*)d_in[5];
    const float* d2_w   = (const float*)d_in[6];
    const float* d2_b   = (const float*)d_in[7];
    const float* d3_w   = (const float*)d_in[8];
    const float* d4_w   = (const float*)d_in[9];
    float* out = (float*)d_out;

    init_kernel<<<(H1N + H2N + 255) / 256, 256>>>(d1_b, d2_b);
    pool_kernel<<<NROIS * FEAT, 224>>>(base_x, rois);
    conv_kernel<<<448, 256>>>(conv_w, conv_b);
    d1_kernel<<<256 * D1_KSPLIT, 256>>>(d1_w);
    d2_kernel<<<256, 256>>>(d2_w);
    head_kernel<<<NROIS, 256>>>(d3_w, d4_w, out);
}

// round 4
// speedup vs baseline: 1.7457x; 1.2237x over previous
#include <cuda_runtime.h>
#include <math.h>

#define POOLN 7
#define NROIS 4
#define FEAT 2048
#define RED 512
#define FLATN (RED * 49)      // 25088 = 14 * 1792
#define H1N 4096
#define H2N 2048
#define NCLS 21
#define NREG 80
#define IMG 128

#define D1_CHUNK 1792
#define D1_KSPLIT 14          // 14 splits * 1792 = 25088

// ---------------- scratch (device globals; no allocations allowed) -------
__device__ float g_pooled[NROIS * 49 * FEAT];   // [r][ph][pw][c]  c fastest
__device__ float g_flat[NROIS * FLATN];         // [r][o*49 + ph*7 + pw]
__device__ float g_h1[NROIS * H1N];             // pre-relu, bias-seeded
__device__ float g_h2[NROIS * H2N];             // pre-relu, bias-seeded
__device__ float g_logits[NROIS * NCLS];

__device__ __forceinline__ float wsum(float v) {
#pragma unroll
    for (int o = 16; o > 0; o >>= 1) v += __shfl_xor_sync(0xffffffffu, v, o);
    return v;
}

// ---------------- kernel 0: seed h1/h2 with biases -------------------------
__global__ __launch_bounds__(256) void init_kernel(
    const float* __restrict__ d1_b, const float* __restrict__ d2_b) {
    int i = blockIdx.x * 256 + threadIdx.x;
    if (i < H1N) {
        float b = d1_b[i];
#pragma unroll
        for (int rr = 0; rr < 4; rr++) g_h1[rr * H1N + i] = b;
    } else if (i < H1N + H2N) {
        int j = i - H1N;
        float b = d2_b[j];
#pragma unroll
        for (int rr = 0; rr < 4; rr++) g_h2[rr * H2N + j] = b;
    }
}

// ---------------- kernel 1: ROI adaptive avg pool (2 channels / block) ----
__global__ __launch_bounds__(224) void pool_kernel(
    const float* __restrict__ x, const int* __restrict__ rois) {
    int blk = blockIdx.x;
    int r = blk & 3;
    int c0 = (blk >> 2) * 2;
    int wid = threadIdx.x >> 5;
    int lane = threadIdx.x & 31;

    int x0 = rois[r * 4 + 0];
    int y0 = rois[r * 4 + 1];
    int hh = rois[r * 4 + 2];
    int ww = rois[r * 4 + 3];
    int Hc = ww;
    int Wc = hh;

    int ph = wid;
    int hs = (ph * Hc) / 7;
    int he = ((ph + 1) * Hc + 6) / 7;

    float acc[2][7];
#pragma unroll
    for (int cc = 0; cc < 2; cc++)
#pragma unroll
        for (int pw = 0; pw < 7; pw++) acc[cc][pw] = 0.f;

    const float* base0 = x + (size_t)c0 * (IMG * IMG) + (size_t)x0 * IMG + y0;
    const float* base1 = base0 + IMG * IMG;

    for (int b = lane; b < Wc; b += 32) {
        float t0 = 0.f, t1 = 0.f, t2 = 0.f, t3 = 0.f;
        float u0 = 0.f, u1 = 0.f, u2 = 0.f, u3 = 0.f;
        int a = hs;
        for (; a + 3 < he; a += 4) {
            t0 += base0[(a + 0) * IMG + b];
            t1 += base0[(a + 1) * IMG + b];
            t2 += base0[(a + 2) * IMG + b];
            t3 += base0[(a + 3) * IMG + b];
            u0 += base1[(a + 0) * IMG + b];
            u1 += base1[(a + 1) * IMG + b];
            u2 += base1[(a + 2) * IMG + b];
            u3 += base1[(a + 3) * IMG + b];
        }
        for (; a < he; a++) {
            t0 += base0[a * IMG + b];
            u0 += base1[a * IMG + b];
        }
        float s0 = (t0 + t1) + (t2 + t3);
        float s1 = (u0 + u1) + (u2 + u3);
#pragma unroll
        for (int pw = 0; pw < 7; pw++) {
            int ws = (pw * Wc) / 7;
            int we = ((pw + 1) * Wc + 6) / 7;
            if (b >= ws && b < we) { acc[0][pw] += s0; acc[1][pw] += s1; }
        }
    }

#pragma unroll
    for (int pw = 0; pw < 7; pw++) {
        float v0 = wsum(acc[0][pw]);
        float v1 = wsum(acc[1][pw]);
        if (lane == 0) {
            int ws = (pw * Wc) / 7;
            int we = ((pw + 1) * Wc + 6) / 7;
            float inv = 1.f / (float)((he - hs) * (we - ws));
            int ob = ((r * 7 + ph) * 7 + pw) * FEAT;
            g_pooled[ob + c0 + 0] = v0 * inv;
            g_pooled[ob + c0 + 1] = v1 * inv;
        }
    }
}

// ---------------- kernel 2: 1x1 conv, all 4 ROIs per block ----------------
// grid = 32 o-splits * 7 ph = 224 blocks. Warp owns 2 o rows; acc[2][4][7].
// Weights read 7x from L2 (28MB total) instead of 28x.
__global__ __launch_bounds__(256) void conv_kernel(
    const float* __restrict__ conv_w, const float* __restrict__ conv_b) {
    __shared__ float smact[4 * 7 * 256];   // 28 KB  [r][pw][k]
    int ph = blockIdx.x % 7;
    int osplit = blockIdx.x / 7;
    int wid = threadIdx.x >> 5;
    int lane = threadIdx.x & 31;
    int o = osplit * 16 + wid * 2;

    float acc[2][4][7];
#pragma unroll
    for (int j = 0; j < 2; j++)
#pragma unroll
        for (int rr = 0; rr < 4; rr++)
#pragma unroll
            for (int pw = 0; pw < 7; pw++) acc[j][rr][pw] = 0.f;

    for (int kc = 0; kc < 8; kc++) {
        __syncthreads();
        // fill 4r x 7pw x 256k slice (float4)
        for (int i = threadIdx.x; i < 1792; i += 256) {
            int rr = i / 448;
            int rem = i - rr * 448;
            int pw = rem / 64;
            int k4 = rem - pw * 64;
            *(float4*)(smact + (rr * 7 + pw) * 256 + k4 * 4) =
                *(const float4*)(g_pooled + (size_t)((rr * 7 + ph) * 7 + pw) * FEAT +
                                 kc * 256 + k4 * 4);
        }
        __syncthreads();
#pragma unroll
        for (int it = 0; it < 2; it++) {
            int k = lane * 4 + it * 128;
            float4 w0 = *(const float4*)(conv_w + (size_t)(o + 0) * FEAT + kc * 256 + k);
            float4 w1 = *(const float4*)(conv_w + (size_t)(o + 1) * FEAT + kc * 256 + k);
#pragma unroll
            for (int rr = 0; rr < 4; rr++) {
#pragma unroll
                for (int pw = 0; pw < 7; pw++) {
                    float4 f = *(const float4*)(smact + (rr * 7 + pw) * 256 + k);
                    acc[0][rr][pw] += w0.x * f.x + w0.y * f.y + w0.z * f.z + w0.w * f.w;
                    acc[1][rr][pw] += w1.x * f.x + w1.y * f.y + w1.z * f.z + w1.w * f.w;
                }
            }
        }
    }

#pragma unroll
    for (int j = 0; j < 2; j++) {
        float b = conv_b[o + j];
#pragma unroll
        for (int rr = 0; rr < 4; rr++) {
#pragma unroll
            for (int pw = 0; pw < 7; pw++) {
                float v = wsum(acc[j][rr][pw]);
                if (lane == 0)
                    g_flat[(size_t)rr * FLATN + (o + j) * 49 + ph * 7 + pw] = v + b;
            }
        }
    }
}

// ---------------- kernel 3: dense1 (K=25088, 4096 out), K-split 14 --------
// grid = 256 rowblocks * 14 ksplits = 3584 blocks; one 1792-chunk per block;
// each warp owns 2 output rows, weights streamed via __ldcs.
__global__ __launch_bounds__(256) void d1_kernel(const float* __restrict__ d1_w) {
    __shared__ float smf[4 * D1_CHUNK];   // 28 KB
    int ks = blockIdx.x % D1_KSPLIT;
    int rowblk = blockIdx.x / D1_KSPLIT;
    int wid = threadIdx.x >> 5;
    int lane = threadIdx.x & 31;
    int j0 = rowblk * 16 + wid * 2;
    int kb = ks * D1_CHUNK;

    // fill activations (float4)
    for (int i = threadIdx.x; i < 1792; i += 256) {   // 1792 float4 = 7168 floats
        int rr = i / 448;
        int k4 = i - rr * 448;
        *(float4*)(smf + rr * D1_CHUNK + k4 * 4) =
            *(const float4*)(g_flat + (size_t)rr * FLATN + kb + k4 * 4);
    }
    __syncthreads();

    float a00 = 0.f, a01 = 0.f, a02 = 0.f, a03 = 0.f;
    float a10 = 0.f, a11 = 0.f, a12 = 0.f, a13 = 0.f;

    const float* wp0 = d1_w + (size_t)(j0 + 0) * FLATN + kb;
    const float* wp1 = d1_w + (size_t)(j0 + 1) * FLATN + kb;
#pragma unroll
    for (int it = 0; it < 14; it++) {
        int k = lane * 4 + it * 128;
        float4 w0 = __ldcs((const float4*)(wp0 + k));
        float4 w1 = __ldcs((const float4*)(wp1 + k));
        float4 f0 = *(const float4*)(smf + 0 * D1_CHUNK + k);
        float4 f1 = *(const float4*)(smf + 1 * D1_CHUNK + k);
        float4 f2 = *(const float4*)(smf + 2 * D1_CHUNK + k);
        float4 f3 = *(const float4*)(smf + 3 * D1_CHUNK + k);
        a00 += w0.x * f0.x + w0.y * f0.y + w0.z * f0.z + w0.w * f0.w;
        a01 += w0.x * f1.x + w0.y * f1.y + w0.z * f1.z + w0.w * f1.w;
        a02 += w0.x * f2.x + w0.y * f2.y + w0.z * f2.z + w0.w * f2.w;
        a03 += w0.x * f3.x + w0.y * f3.y + w0.z * f3.z + w0.w * f3.w;
        a10 += w1.x * f0.x + w1.y * f0.y + w1.z * f0.z + w1.w * f0.w;
        a11 += w1.x * f1.x + w1.y * f1.y + w1.z * f1.z + w1.w * f1.w;
        a12 += w1.x * f2.x + w1.y * f2.y + w1.z * f2.z + w1.w * f2.w;
        a13 += w1.x * f3.x + w1.y * f3.y + w1.z * f3.z + w1.w * f3.w;
    }

    a00 = wsum(a00); a01 = wsum(a01); a02 = wsum(a02); a03 = wsum(a03);
    a10 = wsum(a10); a11 = wsum(a11); a12 = wsum(a12); a13 = wsum(a13);
    if (lane == 0) {
        atomicAdd(&g_h1[0 * H1N + j0 + 0], a00);
        atomicAdd(&g_h1[1 * H1N + j0 + 0], a01);
        atomicAdd(&g_h1[2 * H1N + j0 + 0], a02);
        atomicAdd(&g_h1[3 * H1N + j0 + 0], a03);
        atomicAdd(&g_h1[0 * H1N + j0 + 1], a10);
        atomicAdd(&g_h1[1 * H1N + j0 + 1], a11);
        atomicAdd(&g_h1[2 * H1N + j0 + 1], a12);
        atomicAdd(&g_h1[3 * H1N + j0 + 1], a13);
    }
}

// ---------------- kernel 4: dense2 (K=4096, 2048 out), K-split 4 ----------
// grid = 128 rowblocks * 4 = 512 blocks; smem 16KB; 2 rows per warp.
__global__ __launch_bounds__(256) void d2_kernel(const float* __restrict__ d2_w) {
    __shared__ float smh[4 * 1024];   // 16 KB
    int ks = blockIdx.x & 3;
    int rowblk = blockIdx.x >> 2;
    int wid = threadIdx.x >> 5;
    int lane = threadIdx.x & 31;
    int j0 = rowblk * 16 + wid * 2;
    int kb = ks * 1024;

    for (int i = threadIdx.x; i < 1024; i += 256) {   // float4 units
        int rr = i >> 8;
        int k4 = i & 255;
        float4 v = *(const float4*)(g_h1 + (size_t)rr * H1N + kb + k4 * 4);
        v.x = fmaxf(v.x, 0.f); v.y = fmaxf(v.y, 0.f);
        v.z = fmaxf(v.z, 0.f); v.w = fmaxf(v.w, 0.f);
        *(float4*)(smh + rr * 1024 + k4 * 4) = v;
    }
    __syncthreads();

    float a00 = 0.f, a01 = 0.f, a02 = 0.f, a03 = 0.f;
    float a10 = 0.f, a11 = 0.f, a12 = 0.f, a13 = 0.f;

    const float* wp0 = d2_w + (size_t)(j0 + 0) * H1N + kb;
    const float* wp1 = d2_w + (size_t)(j0 + 1) * H1N + kb;
#pragma unroll
    for (int it = 0; it < 8; it++) {
        int k = lane * 4 + it * 128;
        float4 w0 = __ldcs((const float4*)(wp0 + k));
        float4 w1 = __ldcs((const float4*)(wp1 + k));
        float4 f0 = *(const float4*)(smh + 0 * 1024 + k);
        float4 f1 = *(const float4*)(smh + 1 * 1024 + k);
        float4 f2 = *(const float4*)(smh + 2 * 1024 + k);
        float4 f3 = *(const float4*)(smh + 3 * 1024 + k);
        a00 += w0.x * f0.x + w0.y * f0.y + w0.z * f0.z + w0.w * f0.w;
        a01 += w0.x * f1.x + w0.y * f1.y + w0.z * f1.z + w0.w * f1.w;
        a02 += w0.x * f2.x + w0.y * f2.y + w0.z * f2.z + w0.w * f2.w;
        a03 += w0.x * f3.x + w0.y * f3.y + w0.z * f3.z + w0.w * f3.w;
        a10 += w1.x * f0.x + w1.y * f0.y + w1.z * f0.z + w1.w * f0.w;
        a11 += w1.x * f1.x + w1.y * f1.y + w1.z * f1.z + w1.w * f1.w;
        a12 += w1.x * f2.x + w1.y * f2.y + w1.z * f2.z + w1.w * f2.w;
        a13 += w1.x * f3.x + w1.y * f3.y + w1.z * f3.z + w1.w * f3.w;
    }

    a00 = wsum(a00); a01 = wsum(a01); a02 = wsum(a02); a03 = wsum(a03);
    a10 = wsum(a10); a11 = wsum(a11); a12 = wsum(a12); a13 = wsum(a13);
    if (lane == 0) {
        atomicAdd(&g_h2[0 * H2N + j0 + 0], a00);
        atomicAdd(&g_h2[1 * H2N + j0 + 0], a01);
        atomicAdd(&g_h2[2 * H2N + j0 + 0], a02);
        atomicAdd(&g_h2[3 * H2N + j0 + 0], a03);
        atomicAdd(&g_h2[0 * H2N + j0 + 1], a10);
        atomicAdd(&g_h2[1 * H2N + j0 + 1], a11);
        atomicAdd(&g_h2[2 * H2N + j0 + 1], a12);
        atomicAdd(&g_h2[3 * H2N + j0 + 1], a13);
    }
}

// ---------------- kernel 5: heads (52 blocks) ------------------------------
// grid = 4 r * 13 rowgroups; 8 warps, one output row each (101 rows total).
__global__ __launch_bounds__(256) void head_kernel(
    const float* __restrict__ d3_w, const float* __restrict__ d4_w,
    float* __restrict__ out) {
    __shared__ float smh[H2N];
    int r = blockIdx.x & 3;
    int grp = blockIdx.x >> 2;
    int wid = threadIdx.x >> 5;
    int lane = threadIdx.x & 31;

    for (int i = threadIdx.x; i < H2N / 4; i += 256) {
        float4 v = *(const float4*)(g_h2 + (size_t)r * H2N + i * 4);
        v.x = fmaxf(v.x, 0.f); v.y = fmaxf(v.y, 0.f);
        v.z = fmaxf(v.z, 0.f); v.w = fmaxf(v.w, 0.f);
        *(float4*)(smh + i * 4) = v;
    }
    __syncthreads();

    int row = grp * 8 + wid;
    if (row >= NCLS + NREG) return;
    const float* wrow = (row < NCLS)
                            ? d3_w + (size_t)row * H2N
                            : d4_w + (size_t)(row - NCLS) * H2N;
    float a = 0.f;
#pragma unroll
    for (int it = 0; it < 16; it++) {
        int k = lane * 4 + it * 128;
        float4 w = __ldcs((const float4*)(wrow + k));
        float4 f = *(const float4*)(smh + k);
        a += w.x * f.x + w.y * f.y + w.z * f.z + w.w * f.w;
    }
    a = wsum(a);
    if (lane == 0) {
        if (row < NCLS) g_logits[r * NCLS + row] = a;
        else out[NROIS * NCLS + r * NREG + (row - NCLS)] = a;
    }
}

// ---------------- kernel 6: softmax over class logits ----------------------
__global__ __launch_bounds__(128) void softmax_kernel(float* __restrict__ out) {
    int r = threadIdx.x >> 5;
    int lane = threadIdx.x & 31;
    float v = (lane < NCLS) ? g_logits[r * NCLS + lane] : -INFINITY;
    float m = v;
#pragma unroll
    for (int o = 16; o > 0; o >>= 1)
        m = fmaxf(m, __shfl_xor_sync(0xffffffffu, m, o));
    float e = (lane < NCLS) ? expf(v - m) : 0.f;
    float s = wsum(e);
    if (lane < NCLS) out[r * NCLS + lane] = e / s;
}

// ---------------- launch ---------------------------------------------------
extern "C" void kernel_launch(void* const* d_in, const int* in_sizes, int n_in,
                              void* d_out, int out_size) {
    const float* base_x = (const float*)d_in[0];
    const int*   rois   = (const int*)d_in[1];
    const float* conv_w = (const float*)d_in[2];
    const float* conv_b = (const float*)d_in[3];
    const float* d1_w   = (const float*)d_in[4];
    const float* d1_b   = (const float*)d_in[5];
    const float* d2_w   = (const float*)d_in[6];
    const float* d2_b   = (const float*)d_in[7];
    const float* d3_w   = (const float*)d_in[8];
    const float* d4_w   = (const float*)d_in[9];
    float* out = (float*)d_out;

    init_kernel<<<(H1N + H2N + 255) / 256, 256>>>(d1_b, d2_b);
    pool_kernel<<<NROIS * (FEAT / 2), 224>>>(base_x, rois);
    conv_kernel<<<224, 256>>>(conv_w, conv_b);
    d1_kernel<<<256 * D1_KSPLIT, 256>>>(d1_w);
    d2_kernel<<<512, 256>>>(d2_w);
    head_kernel<<<52, 256>>>(d3_w, d4_w, out);
    softmax_kernel<<<1, 128>>>(out);
}

// round 5
// speedup vs baseline: 1.8184x; 1.0416x over previous
#include <cuda_runtime.h>
#include <math.h>

#define POOLN 7
#define NROIS 4
#define FEAT 2048
#define RED 512
#define FLATN (RED * 49)      // 25088 = 14 * 1792
#define H1N 4096
#define H2N 2048
#define NCLS 21
#define NREG 80
#define IMG 128

#define D1_CHUNK 1792
#define D1_KSPLIT 14          // 14 splits * 1792 = 25088

// packed f32x2 helpers (FFMA2 path — PTX-only)
#define PACK2(u, a, b) asm("mov.b64 %0, {%1, %2};" : "=l"(u) : "f"(a), "f"(b))
#define FMA2(acc, u, v) \
    asm("fma.rn.f32x2 %0, %1, %2, %0;" : "+l"(acc) : "l"(u), "l"(v))
#define UNPACK2(a, b, u) asm("mov.b64 {%0, %1}, %2;" : "=f"(a), "=f"(b) : "l"(u))

// ---------------- scratch (device globals; no allocations allowed) -------
__device__ float g_pooled[NROIS * 49 * FEAT];   // [r][ph][pw][c]  c fastest
__device__ float g_flat[NROIS * FLATN];         // [r][o*49 + ph*7 + pw]
__device__ float g_h1[NROIS * H1N];             // pre-relu, bias-seeded
__device__ float g_h2[NROIS * H2N];             // pre-relu, bias-seeded
__device__ float g_logits[NROIS * NCLS];

__device__ __forceinline__ float wsum(float v) {
#pragma unroll
    for (int o = 16; o > 0; o >>= 1) v += __shfl_xor_sync(0xffffffffu, v, o);
    return v;
}

// ---------------- kernel 1: ROI adaptive avg pool --------------------------
// 4 channels / block, float4 column loads. grid = 4r * 512 = 2048 blocks.
// Lane owns one aligned float4 column group; warp ph owns one bin row.
__global__ __launch_bounds__(224) void pool_kernel(
    const float* __restrict__ x, const int* __restrict__ rois) {
    int blk = blockIdx.x;
    int r = blk & 3;
    int c0 = (blk >> 2) * 4;
    int wid = threadIdx.x >> 5;
    int lane = threadIdx.x & 31;

    int x0 = rois[r * 4 + 0];
    int y0 = rois[r * 4 + 1];
    int Wc = rois[r * 4 + 2];   // cols count (axis2 = y:y+h)
    int Hc = rois[r * 4 + 3];   // rows count (axis1 = x:x+w)

    int ph = wid;
    int hs = (ph * Hc) / 7;
    int he = ((ph + 1) * Hc + 6) / 7;

    int ya = y0 & ~3;
    int nl = (y0 + Wc - ya + 3) >> 2;
    int nlmax = (IMG - ya) >> 2;
    if (nl > nlmax) nl = nlmax;

    float4 s0 = {0,0,0,0}, s1 = {0,0,0,0}, s2 = {0,0,0,0}, s3 = {0,0,0,0};

    if (lane < nl) {
        const float* pl0 = x + (size_t)(c0 + 0) * (IMG * IMG) +
                           (size_t)x0 * IMG + ya + 4 * lane;
        const float* pl1 = pl0 + IMG * IMG;
        const float* pl2 = pl1 + IMG * IMG;
        const float* pl3 = pl2 + IMG * IMG;
        int a = hs;
        for (; a + 1 < he; a += 2) {
            float4 v00 = *(const float4*)(pl0 + (a + 0) * IMG);
            float4 v10 = *(const float4*)(pl1 + (a + 0) * IMG);
            float4 v20 = *(const float4*)(pl2 + (a + 0) * IMG);
            float4 v30 = *(const float4*)(pl3 + (a + 0) * IMG);
            float4 v01 = *(const float4*)(pl0 + (a + 1) * IMG);
            float4 v11 = *(const float4*)(pl1 + (a + 1) * IMG);
            float4 v21 = *(const float4*)(pl2 + (a + 1) * IMG);
            float4 v31 = *(const float4*)(pl3 + (a + 1) * IMG);
            s0.x += v00.x + v01.x; s0.y += v00.y + v01.y;
            s0.z += v00.z + v01.z; s0.w += v00.w + v01.w;
            s1.x += v10.x + v11.x; s1.y += v10.y + v11.y;
            s1.z += v10.z + v11.z; s1.w += v10.w + v11.w;
            s2.x += v20.x + v21.x; s2.y += v20.y + v21.y;
            s2.z += v20.z + v21.z; s2.w += v20.w + v21.w;
            s3.x += v30.x + v31.x; s3.y += v30.y + v31.y;
            s3.z += v30.z + v31.z; s3.w += v30.w + v31.w;
        }
        if (a < he) {
            float4 v0 = *(const float4*)(pl0 + a * IMG);
            float4 v1 = *(const float4*)(pl1 + a * IMG);
            float4 v2 = *(const float4*)(pl2 + a * IMG);
            float4 v3 = *(const float4*)(pl3 + a * IMG);
            s0.x += v0.x; s0.y += v0.y; s0.z += v0.z; s0.w += v0.w;
            s1.x += v1.x; s1.y += v1.y; s1.z += v1.z; s1.w += v1.w;
            s2.x += v2.x; s2.y += v2.y; s2.z += v2.z; s2.w += v2.w;
            s3.x += v3.x; s3.y += v3.y; s3.z += v3.z; s3.w += v3.w;
        }
    }

    float acc[4][7];
#pragma unroll
    for (int cc = 0; cc < 4; cc++)
#pragma unroll
        for (int pw = 0; pw < 7; pw++) acc[cc][pw] = 0.f;

    // scatter the 4 column sums into (possibly overlapping) bins
    float sc[4][4] = {{s0.x, s0.y, s0.z, s0.w}, {s1.x, s1.y, s1.z, s1.w},
                      {s2.x, s2.y, s2.z, s2.w}, {s3.x, s3.y, s3.z, s3.w}};
#pragma unroll
    for (int q = 0; q < 4; q++) {
        int b = ya + 4 * lane + q - y0;
        bool valid = (b >= 0) && (b < Wc);
#pragma unroll
        for (int pw = 0; pw < 7; pw++) {
            int ws = (pw * Wc) / 7;
            int we = ((pw + 1) * Wc + 6) / 7;
            if (valid && b >= ws && b < we) {
#pragma unroll
                for (int cc = 0; cc < 4; cc++) acc[cc][pw] += sc[cc][q];
            }
        }
    }

#pragma unroll
    for (int pw = 0; pw < 7; pw++) {
        float v0 = wsum(acc[0][pw]);
        float v1 = wsum(acc[1][pw]);
        float v2 = wsum(acc[2][pw]);
        float v3 = wsum(acc[3][pw]);
        if (lane == 0) {
            int ws = (pw * Wc) / 7;
            int we = ((pw + 1) * Wc + 6) / 7;
            float inv = 1.f / (float)((he - hs) * (we - ws));
            int ob = ((r * 7 + ph) * 7 + pw) * FEAT + c0;
            g_pooled[ob + 0] = v0 * inv;
            g_pooled[ob + 1] = v1 * inv;
            g_pooled[ob + 2] = v2 * inv;
            g_pooled[ob + 3] = v3 * inv;
        }
    }
}

// ---------------- kernel 2: 1x1 conv + bias-seed h1/h2 --------------------
// grid = 64 o-splits * 7 ph = 448 blocks; warp owns 1 o-row; f32x2 FMA.
__global__ __launch_bounds__(256) void conv_kernel(
    const float* __restrict__ conv_w, const float* __restrict__ conv_b,
    const float* __restrict__ d1_b, const float* __restrict__ d2_b) {
    __shared__ float smact[4 * 7 * 256];   // 28 KB  [r][pw][k]

    // fold former init_kernel: seed g_h1/g_h2 with biases (blocks 0..23)
    {
        int gi = blockIdx.x * 256 + threadIdx.x;
        if (gi < H1N) {
            float b = d1_b[gi];
#pragma unroll
            for (int rr = 0; rr < 4; rr++) g_h1[rr * H1N + gi] = b;
        } else if (gi < H1N + H2N) {
            int j = gi - H1N;
            float b = d2_b[j];
#pragma unroll
            for (int rr = 0; rr < 4; rr++) g_h2[rr * H2N + j] = b;
        }
    }

    int ph = blockIdx.x % 7;
    int osplit = blockIdx.x / 7;
    int wid = threadIdx.x >> 5;
    int lane = threadIdx.x & 31;
    int o = osplit * 8 + wid;

    unsigned long long acc2[4][7];
#pragma unroll
    for (int rr = 0; rr < 4; rr++)
#pragma unroll
        for (int pw = 0; pw < 7; pw++) acc2[rr][pw] = 0ull;

    for (int kc = 0; kc < 8; kc++) {
        __syncthreads();
        for (int i = threadIdx.x; i < 1792; i += 256) {
            int rr = i / 448;
            int rem = i - rr * 448;
            int pw = rem / 64;
            int k4 = rem - pw * 64;
            *(float4*)(smact + (rr * 7 + pw) * 256 + k4 * 4) =
                *(const float4*)(g_pooled + (size_t)((rr * 7 + ph) * 7 + pw) * FEAT +
                                 kc * 256 + k4 * 4);
        }
        __syncthreads();
#pragma unroll
        for (int it = 0; it < 2; it++) {
            int k = lane * 4 + it * 128;
            float4 w = *(const float4*)(conv_w + (size_t)o * FEAT + kc * 256 + k);
            unsigned long long wlo, whi;
            PACK2(wlo, w.x, w.y);
            PACK2(whi, w.z, w.w);
#pragma unroll
            for (int rr = 0; rr < 4; rr++) {
#pragma unroll
                for (int pw = 0; pw < 7; pw++) {
                    ulonglong2 f = *(const ulonglong2*)(smact + (rr * 7 + pw) * 256 + k);
                    FMA2(acc2[rr][pw], wlo, f.x);
                    FMA2(acc2[rr][pw], whi, f.y);
                }
            }
        }
    }

    float b = conv_b[o];
#pragma unroll
    for (int rr = 0; rr < 4; rr++) {
#pragma unroll
        for (int pw = 0; pw < 7; pw++) {
            float lo, hi;
            UNPACK2(lo, hi, acc2[rr][pw]);
            float v = wsum(lo + hi);
            if (lane == 0)
                g_flat[(size_t)rr * FLATN + o * 49 + ph * 7 + pw] = v + b;
        }
    }
}

// ---------------- kernel 3: dense1 (K=25088, 4096 out), K-split 14 --------
__global__ __launch_bounds__(256) void d1_kernel(const float* __restrict__ d1_w) {
    __shared__ float smf[4 * D1_CHUNK];   // 28 KB
    int ks = blockIdx.x % D1_KSPLIT;
    int rowblk = blockIdx.x / D1_KSPLIT;
    int wid = threadIdx.x >> 5;
    int lane = threadIdx.x & 31;
    int j0 = rowblk * 16 + wid * 2;
    int kb = ks * D1_CHUNK;

    for (int i = threadIdx.x; i < 1792; i += 256) {
        int rr = i / 448;
        int k4 = i - rr * 448;
        *(float4*)(smf + rr * D1_CHUNK + k4 * 4) =
            *(const float4*)(g_flat + (size_t)rr * FLATN + kb + k4 * 4);
    }
    __syncthreads();

    unsigned long long a00 = 0, a01 = 0, a02 = 0, a03 = 0;
    unsigned long long a10 = 0, a11 = 0, a12 = 0, a13 = 0;

    const float* wp0 = d1_w + (size_t)(j0 + 0) * FLATN + kb;
    const float* wp1 = d1_w + (size_t)(j0 + 1) * FLATN + kb;
#pragma unroll
    for (int it = 0; it < 14; it++) {
        int k = lane * 4 + it * 128;
        float4 w0 = __ldcs((const float4*)(wp0 + k));
        float4 w1 = __ldcs((const float4*)(wp1 + k));
        unsigned long long w0lo, w0hi, w1lo, w1hi;
        PACK2(w0lo, w0.x, w0.y); PACK2(w0hi, w0.z, w0.w);
        PACK2(w1lo, w1.x, w1.y); PACK2(w1hi, w1.z, w1.w);
        ulonglong2 f0 = *(const ulonglong2*)(smf + 0 * D1_CHUNK + k);
        ulonglong2 f1 = *(const ulonglong2*)(smf + 1 * D1_CHUNK + k);
        ulonglong2 f2 = *(const ulonglong2*)(smf + 2 * D1_CHUNK + k);
        ulonglong2 f3 = *(const ulonglong2*)(smf + 3 * D1_CHUNK + k);
        FMA2(a00, w0lo, f0.x); FMA2(a00, w0hi, f0.y);
        FMA2(a01, w0lo, f1.x); FMA2(a01, w0hi, f1.y);
        FMA2(a02, w0lo, f2.x); FMA2(a02, w0hi, f2.y);
        FMA2(a03, w0lo, f3.x); FMA2(a03, w0hi, f3.y);
        FMA2(a10, w1lo, f0.x); FMA2(a10, w1hi, f0.y);
        FMA2(a11, w1lo, f1.x); FMA2(a11, w1hi, f1.y);
        FMA2(a12, w1lo, f2.x); FMA2(a12, w1hi, f2.y);
        FMA2(a13, w1lo, f3.x); FMA2(a13, w1hi, f3.y);
    }

    float lo, hi, r00, r01, r02, r03, r10, r11, r12, r13;
    UNPACK2(lo, hi, a00); r00 = wsum(lo + hi);
    UNPACK2(lo, hi, a01); r01 = wsum(lo + hi);
    UNPACK2(lo, hi, a02); r02 = wsum(lo + hi);
    UNPACK2(lo, hi, a03); r03 = wsum(lo + hi);
    UNPACK2(lo, hi, a10); r10 = wsum(lo + hi);
    UNPACK2(lo, hi, a11); r11 = wsum(lo + hi);
    UNPACK2(lo, hi, a12); r12 = wsum(lo + hi);
    UNPACK2(lo, hi, a13); r13 = wsum(lo + hi);
    if (lane == 0) {
        atomicAdd(&g_h1[0 * H1N + j0 + 0], r00);
        atomicAdd(&g_h1[1 * H1N + j0 + 0], r01);
        atomicAdd(&g_h1[2 * H1N + j0 + 0], r02);
        atomicAdd(&g_h1[3 * H1N + j0 + 0], r03);
        atomicAdd(&g_h1[0 * H1N + j0 + 1], r10);
        atomicAdd(&g_h1[1 * H1N + j0 + 1], r11);
        atomicAdd(&g_h1[2 * H1N + j0 + 1], r12);
        atomicAdd(&g_h1[3 * H1N + j0 + 1], r13);
    }
}

// ---------------- kernel 4: dense2 (K=4096, 2048 out), K-split 8 ----------
__global__ __launch_bounds__(256) void d2_kernel(const float* __restrict__ d2_w) {
    __shared__ float smh[4 * 512];   // 8 KB
    int ks = blockIdx.x & 7;
    int rowblk = blockIdx.x >> 3;
    int wid = threadIdx.x >> 5;
    int lane = threadIdx.x & 31;
    int j0 = rowblk * 16 + wid * 2;
    int kb = ks * 512;

    for (int i = threadIdx.x; i < 512; i += 256) {   // float4 units
        int rr = i >> 7;
        int k4 = i & 127;
        float4 v = *(const float4*)(g_h1 + (size_t)rr * H1N + kb + k4 * 4);
        v.x = fmaxf(v.x, 0.f); v.y = fmaxf(v.y, 0.f);
        v.z = fmaxf(v.z, 0.f); v.w = fmaxf(v.w, 0.f);
        *(float4*)(smh + rr * 512 + k4 * 4) = v;
    }
    __syncthreads();

    unsigned long long a00 = 0, a01 = 0, a02 = 0, a03 = 0;
    unsigned long long a10 = 0, a11 = 0, a12 = 0, a13 = 0;

    const float* wp0 = d2_w + (size_t)(j0 + 0) * H1N + kb;
    const float* wp1 = d2_w + (size_t)(j0 + 1) * H1N + kb;
#pragma unroll
    for (int it = 0; it < 4; it++) {
        int k = lane * 4 + it * 128;
        float4 w0 = __ldcs((const float4*)(wp0 + k));
        float4 w1 = __ldcs((const float4*)(wp1 + k));
        unsigned long long w0lo, w0hi, w1lo, w1hi;
        PACK2(w0lo, w0.x, w0.y); PACK2(w0hi, w0.z, w0.w);
        PACK2(w1lo, w1.x, w1.y); PACK2(w1hi, w1.z, w1.w);
        ulonglong2 f0 = *(const ulonglong2*)(smh + 0 * 512 + k);
        ulonglong2 f1 = *(const ulonglong2*)(smh + 1 * 512 + k);
        ulonglong2 f2 = *(const ulonglong2*)(smh + 2 * 512 + k);
        ulonglong2 f3 = *(const ulonglong2*)(smh + 3 * 512 + k);
        FMA2(a00, w0lo, f0.x); FMA2(a00, w0hi, f0.y);
        FMA2(a01, w0lo, f1.x); FMA2(a01, w0hi, f1.y);
        FMA2(a02, w0lo, f2.x); FMA2(a02, w0hi, f2.y);
        FMA2(a03, w0lo, f3.x); FMA2(a03, w0hi, f3.y);
        FMA2(a10, w1lo, f0.x); FMA2(a10, w1hi, f0.y);
        FMA2(a11, w1lo, f1.x); FMA2(a11, w1hi, f1.y);
        FMA2(a12, w1lo, f2.x); FMA2(a12, w1hi, f2.y);
        FMA2(a13, w1lo, f3.x); FMA2(a13, w1hi, f3.y);
    }

    float lo, hi, r00, r01, r02, r03, r10, r11, r12, r13;
    UNPACK2(lo, hi, a00); r00 = wsum(lo + hi);
    UNPACK2(lo, hi, a01); r01 = wsum(lo + hi);
    UNPACK2(lo, hi, a02); r02 = wsum(lo + hi);
    UNPACK2(lo, hi, a03); r03 = wsum(lo + hi);
    UNPACK2(lo, hi, a10); r10 = wsum(lo + hi);
    UNPACK2(lo, hi, a11); r11 = wsum(lo + hi);
    UNPACK2(lo, hi, a12); r12 = wsum(lo + hi);
    UNPACK2(lo, hi, a13); r13 = wsum(lo + hi);
    if (lane == 0) {
        atomicAdd(&g_h2[0 * H2N + j0 + 0], r00);
        atomicAdd(&g_h2[1 * H2N + j0 + 0], r01);
        atomicAdd(&g_h2[2 * H2N + j0 + 0], r02);
        atomicAdd(&g_h2[3 * H2N + j0 + 0], r03);
        atomicAdd(&g_h2[0 * H2N + j0 + 1], r10);
        atomicAdd(&g_h2[1 * H2N + j0 + 1], r11);
        atomicAdd(&g_h2[2 * H2N + j0 + 1], r12);
        atomicAdd(&g_h2[3 * H2N + j0 + 1], r13);
    }
}

// ---------------- kernel 5: heads (52 blocks) ------------------------------
__global__ __launch_bounds__(256) void head_kernel(
    const float* __restrict__ d3_w, const float* __restrict__ d4_w,
    float* __restrict__ out) {
    __shared__ float smh[H2N];
    int r = blockIdx.x & 3;
    int grp = blockIdx.x >> 2;
    int wid = threadIdx.x >> 5;
    int lane = threadIdx.x & 31;

    for (int i = threadIdx.x; i < H2N / 4; i += 256) {
        float4 v = *(const float4*)(g_h2 + (size_t)r * H2N + i * 4);
        v.x = fmaxf(v.x, 0.f); v.y = fmaxf(v.y, 0.f);
        v.z = fmaxf(v.z, 0.f); v.w = fmaxf(v.w, 0.f);
        *(float4*)(smh + i * 4) = v;
    }
    __syncthreads();

    int row = grp * 8 + wid;
    if (row >= NCLS + NREG) return;
    const float* wrow = (row < NCLS)
                            ? d3_w + (size_t)row * H2N
                            : d4_w + (size_t)(row - NCLS) * H2N;
    float a = 0.f;
#pragma unroll
    for (int it = 0; it < 16; it++) {
        int k = lane * 4 + it * 128;
        float4 w = __ldcs((const float4*)(wrow + k));
        float4 f = *(const float4*)(smh + k);
        a += w.x * f.x + w.y * f.y + w.z * f.z + w.w * f.w;
    }
    a = wsum(a);
    if (lane == 0) {
        if (row < NCLS) g_logits[r * NCLS + row] = a;
        else out[NROIS * NCLS + r * NREG + (row - NCLS)] = a;
    }
}

// ---------------- kernel 6: softmax over class logits ----------------------
__global__ __launch_bounds__(128) void softmax_kernel(float* __restrict__ out) {
    int r = threadIdx.x >> 5;
    int lane = threadIdx.x & 31;
    float v = (lane < NCLS) ? g_logits[r * NCLS + lane] : -INFINITY;
    float m = v;
#pragma unroll
    for (int o = 16; o > 0; o >>= 1)
        m = fmaxf(m, __shfl_xor_sync(0xffffffffu, m, o));
    float e = (lane < NCLS) ? expf(v - m) : 0.f;
    float s = wsum(e);
    if (lane < NCLS) out[r * NCLS + lane] = e / s;
}

// ---------------- launch ---------------------------------------------------
extern "C" void kernel_launch(void* const* d_in, const int* in_sizes, int n_in,
                              void* d_out, int out_size) {
    const float* base_x = (const float*)d_in[0];
    const int*   rois   = (const int*)d_in[1];
    const float* conv_w = (const float*)d_in[2];
    const float* conv_b = (const float*)d_in[3];
    const float* d1_w   = (const float*)d_in[4];
    const float* d1_b   = (const float*)d_in[5];
    const float* d2_w   = (const float*)d_in[6];
    const float* d2_b   = (const float*)d_in[7];
    const float* d3_w   = (const float*)d_in[8];
    const float* d4_w   = (const float*)d_in[9];
    float* out = (float*)d_out;

    pool_kernel<<<NROIS * (FEAT / 4), 224>>>(base_x, rois);
    conv_kernel<<<448, 256>>>(conv_w, conv_b, d1_b, d2_b);
    d1_kernel<<<256 * D1_KSPLIT, 256>>>(d1_w);
    d2_kernel<<<1024, 256>>>(d2_w);
    head_kernel<<<52, 256>>>(d3_w, d4_w, out);
    softmax_kernel<<<1, 128>>>(out);
}